// round 14
// baseline (speedup 1.0000x reference)
#include <cuda_runtime.h>
#include <cuda_fp16.h>

// Fused NeRF MLP forward, fp16 mma.sync.m16n8k16, fp32 accum.
// 128 points/CTA, 512 threads (16 warps = 4 Mgrp x 4 Ngrp), warp tile 32x32.
// Weights pre-packed as pre-swizzled 16KB smem images; staged via
// cp.async.bulk (one instruction per chunk) through a flat double-buffered
// mbarrier pipeline that prefetches across layer boundaries.

#define MTILE 128
#define BLK   512
#define NCH   73

// strides in halves (row stride bytes % 128 == 16 -> conflict-free ldmatrix)
#define HSTH  264
#define XSTH  72
#define DSTH  72
#define HIDH  136

// ---- packed weight buffer: sequence of 16KB (8192-half) chunk images ----
#define SEG0   0        // L0 xyz: 2 images (nh0, nh1)
#define SEG1   16384    // 8 images (nh-major, 4 chunks each)
#define SEG2   81920
#define SEG3   147456
#define SEG4X  212992   // 2 images
#define SEG4H  229376
#define SEG5   294912
#define SEG6   360448
#define SEG7   425984
#define SEGF   491520
#define SEGR1  557056   // 4 images
#define SEGR1D 589824   // 1 image
#define WH_TOTAL 598016
__device__ __align__(16) __half g_wh[WH_TOTAL];

// ---- smem byte offsets ----
#define OFF_H0   0                          // 128*264*2 = 67584
#define OFF_H1   67584
#define OFF_X    135168                     // 128*72*2 = 18432
#define OFF_D    153600
#define OFF_W0   172032                     // 16384
#define OFF_W1   188416
#define OFF_SIG  204800                     // 512
#define OFF_MB   205312                     // 2 x 8B mbarriers
#define OFF_LIST 205328                     // 73 x 4B
#define OFF_HID  OFF_X                      // aliases X/D region
#define SMEM_BYTES 205824

struct Params {
    const float* x;
    const float* b[8];
    const float *bf, *ws, *bs, *br1, *wr2, *br2;
    float* out;
};

// ============ pack kernel: weights -> pre-swizzled 16KB chunk images ========
struct PSeg { const float* src; int ldn; int k0; int k_real; int nchunks; int dst; };
struct PackArgs { PSeg s[12]; };

__global__ void pack_weights(PackArgs pa) {
    const int idx = blockIdx.x * blockDim.x + threadIdx.x;
    if (idx >= WH_TOTAL) return;
    int si = 0;
#pragma unroll
    for (int i = 1; i < 12; ++i)
        if (idx >= pa.s[i].dst) si = i;
    const PSeg g = pa.s[si];
    const int local = idx - g.dst;
    const int img   = local >> 13;          // 8192 halves per image
    const int w_in  = local & 8191;
    const int pr    = w_in >> 8;            // 256 halves per pair-row
    const int wh    = w_in & 255;
    const int cs_sw = wh >> 3;
    const int h     = wh & 7;
    const int cs    = cs_sw ^ ((pr & 3) << 1);     // undo swizzle -> source chunk
    const int nh    = img / g.nchunks;
    const int c     = img % g.nchunks;
    const int n     = nh * 128 + cs * 4 + (h >> 1);
    const int k     = (c * 32 + pr) * 2 + (h & 1);
    const float v = (k < g.k_real) ? g.src[(g.k0 + k) * g.ldn + n] : 0.0f;
    g_wh[idx] = __float2half_rn(v);
}

// ========================= device primitives ================================
__device__ __forceinline__ void mma16(float c[4], const unsigned a[4],
                                      unsigned b0, unsigned b1) {
    asm volatile(
        "mma.sync.aligned.m16n8k16.row.col.f32.f16.f16.f32 "
        "{%0,%1,%2,%3}, {%4,%5,%6,%7}, {%8,%9}, {%0,%1,%2,%3};\n"
        : "+f"(c[0]), "+f"(c[1]), "+f"(c[2]), "+f"(c[3])
        : "r"(a[0]), "r"(a[1]), "r"(a[2]), "r"(a[3]), "r"(b0), "r"(b1));
}
__device__ __forceinline__ void ldsm_x4(unsigned r[4], const __half* p) {
    unsigned addr = (unsigned)__cvta_generic_to_shared(p);
    asm volatile("ldmatrix.sync.aligned.m8n8.x4.shared.b16 {%0,%1,%2,%3}, [%4];\n"
        : "=r"(r[0]), "=r"(r[1]), "=r"(r[2]), "=r"(r[3]) : "r"(addr));
}
__device__ __forceinline__ void mbar_init1(unsigned m) {
    asm volatile("mbarrier.init.shared.b64 [%0], %1;" :: "r"(m), "r"(1u) : "memory");
}
__device__ __forceinline__ void bulk_issue(unsigned dst, const void* src,
                                           unsigned mbar) {
    asm volatile("mbarrier.arrive.expect_tx.shared.b64 _, [%0], %1;"
                 :: "r"(mbar), "r"(16384u) : "memory");
    asm volatile(
        "cp.async.bulk.shared::cluster.global.mbarrier::complete_tx::bytes "
        "[%0], [%1], %2, [%3];"
        :: "r"(dst), "l"(src), "r"(16384u), "r"(mbar) : "memory");
}
__device__ __forceinline__ void mwait(unsigned m, int parity) {
    unsigned done;
    do {
        asm volatile("{\n\t.reg .pred p;\n\t"
            "mbarrier.try_wait.parity.acquire.cta.shared::cta.b64 p, [%1], %2, 0x989680;\n\t"
            "selp.b32 %0, 1, 0, p;\n\t}"
            : "=r"(done) : "r"(m), "r"((unsigned)parity) : "memory");
    } while (!done);
}

// One 64-k chunk. sW words: [pair_row 0..31][128],
// column permutation P(j,n) = cb + n*4 + j, chunk swizzle (pr&3)<<1.
__device__ __forceinline__ void mma_chunk4(float acc[2][4][4],
        const __half* __restrict__ sA, int astH, int kbH,
        const float* __restrict__ sW, int mg, int ng, int lane)
{
    const int g    = lane >> 2;
    const int tig  = lane & 3;
    const int mat  = lane >> 3;
    const int arow = ((mat & 1) << 3) + (lane & 7);
    const int akof = (mat >> 1) << 3;
    const int rb   = mg * 32;
    const int c0   = (((ng << 3) + g) ^ (tig << 1)) << 2;

#pragma unroll
    for (int s = 0; s < 4; ++s) {
        unsigned a[2][4];
#pragma unroll
        for (int m = 0; m < 2; ++m) {
            const __half* ap = sA + (rb + 16 * m + arow) * astH
                                  + kbH + 16 * s + akof;
            ldsm_x4(a[m], ap);
        }
        const float* r0p = sW + (8 * s + tig) * 128;
        const float* r1p = r0p + 4 * 128;
        const float4 q0 = *(const float4*)(r0p + c0);
        const float4 q1 = *(const float4*)(r1p + c0);
        const unsigned* b0 = (const unsigned*)&q0;
        const unsigned* b1 = (const unsigned*)&q1;
#pragma unroll
        for (int j = 0; j < 4; ++j) {
            mma16(acc[0][j], a[0], b0[j], b1[j]);
            mma16(acc[1][j], a[1], b0[j], b1[j]);
        }
    }
}

// epilogue: 8 contiguous cols per thread-row -> one STS.128 per row.
__device__ __forceinline__ void epi(float acc[2][4][4],
        __half* __restrict__ sDst, int dstH,
        const float* __restrict__ gB, int cb,
        bool relu, int mg, int lane)
{
    const int g   = lane >> 2;
    const int tig = lane & 3;
    const int rb  = mg * 32;
    const int cbase = cb + 8 * tig;
    const float4 bA = *(const float4*)(gB + cbase);
    const float4 bB = *(const float4*)(gB + cbase + 4);
    const float bias[8] = { bA.x, bA.y, bA.z, bA.w, bB.x, bB.y, bB.z, bB.w };
#pragma unroll
    for (int m = 0; m < 2; ++m) {
#pragma unroll
        for (int h = 0; h < 2; ++h) {
            const int row = rb + 16 * m + 8 * h + g;
            __half hv[8];
#pragma unroll
            for (int j = 0; j < 4; ++j) {
                float v0 = acc[m][j][2 * h + 0] + bias[j];
                float v1 = acc[m][j][2 * h + 1] + bias[4 + j];
                if (relu) { v0 = fmaxf(v0, 0.0f); v1 = fmaxf(v1, 0.0f); }
                hv[j]     = __float2half_rn(v0);
                hv[4 + j] = __float2half_rn(v1);
            }
            *(uint4*)(sDst + row * dstH + cbase) = *(const uint4*)hv;
        }
    }
}

__device__ __forceinline__ void zacc(float acc[2][4][4]) {
#pragma unroll
    for (int m = 0; m < 2; ++m)
#pragma unroll
        for (int j = 0; j < 4; ++j)
#pragma unroll
            for (int q = 0; q < 4; ++q) acc[m][j][q] = 0.0f;
}

__global__ void __launch_bounds__(BLK, 1) nerf_fused(Params p) {
    extern __shared__ unsigned char sm[];
    const unsigned sb = (unsigned)__cvta_generic_to_shared(sm);
    __half* hbuf0 = (__half*)(sm + OFF_H0);
    __half* hbuf1 = (__half*)(sm + OFF_H1);
    __half* sX    = (__half*)(sm + OFF_X);
    __half* sDr   = (__half*)(sm + OFF_D);
    __half* sHid  = (__half*)(sm + OFF_HID);
    float*  sSig  = (float*) (sm + OFF_SIG);
    unsigned* qlist = (unsigned*)(sm + OFF_LIST);

    const unsigned mb0 = sb + OFF_MB, mb1 = sb + OFF_MB + 8;
    const unsigned wa0 = sb + OFF_W0, wa1 = sb + OFF_W1;
    const float* wbp0 = (const float*)(sm + OFF_W0);
    const float* wbp1 = (const float*)(sm + OFF_W1);

    const int tid  = threadIdx.x;
    const int wid  = tid >> 5;
    const int lane = tid & 31;
    const int mg   = wid & 3;
    const int ng   = wid >> 2;
    const int p0   = blockIdx.x * MTILE;

    // ---- init mbarriers + build chunk-source list (byte offsets) ----
    if (tid == 0) {
        mbar_init1(mb0);
        mbar_init1(mb1);
        asm volatile("fence.proxy.async.shared::cta;" ::: "memory");
        int i = 0;
        qlist[i++] = SEG0 * 2;
        qlist[i++] = (SEG0 + 8192) * 2;
        const int ws[8] = { SEG1, SEG2, SEG3, SEG4H, SEG5, SEG6, SEG7, SEGF };
        for (int L = 1; L <= 8; ++L)
            for (int nh = 0; nh < 2; ++nh) {
                if (L == 4) qlist[i++] = (SEG4X + nh * 8192) * 2;
                for (int c = 0; c < 4; ++c)
                    qlist[i++] = (ws[L - 1] + (nh * 4 + c) * 8192) * 2;
            }
        for (int c = 0; c < 4; ++c) qlist[i++] = (SEGR1 + c * 8192) * 2;
        qlist[i++] = SEGR1D * 2;
    }

    // ---- raw x into weight-buf scratch, then positional encodings ----
    float* xr = (float*)(sm + OFF_W0);
    for (int idx = tid; idx < MTILE * 6; idx += BLK)
        xr[idx] = p.x[p0 * 6 + idx];
    __syncthreads();

    for (int idx = tid; idx < MTILE * 64; idx += BLK) {
        const int r = idx >> 6, c = idx & 63;
        float v = 0.0f;
        if (c < 3) v = xr[r * 6 + c];
        else if (c < 63) {
            const int q = c - 3, f = q / 6, rem = q % 6;
            const float ang = xr[r * 6 + (rem % 3)] * (float)(1 << f);
            v = (rem < 3) ? sinf(ang) : cosf(ang);
        }
        sX[r * XSTH + c] = __float2half_rn(v);
    }
    for (int idx = tid; idx < MTILE * 64; idx += BLK) {
        const int r = idx >> 6, c = idx & 63;
        float v = 0.0f;
        if (c < 3) v = xr[r * 6 + 3 + c];
        else if (c < 27) {
            const int q = c - 3, f = q / 6, rem = q % 6;
            const float ang = xr[r * 6 + 3 + (rem % 3)] * (float)(1 << f);
            v = (rem < 3) ? sinf(ang) : cosf(ang);
        }
        sDr[r * DSTH + c] = __float2half_rn(v);
    }
    __syncthreads();

    // ---- start the pipeline: 2 chunks in flight ----
    if (tid == 0) {
        bulk_issue(wa0, (const char*)g_wh + qlist[0], mb0);
        bulk_issue(wa1, (const char*)g_wh + qlist[1], mb1);
    }
    int sl = 0, ph0 = 0, ph1 = 0, qi = 2;

#define PIPE_WAIT() do {                                         \
        if (sl) { mwait(mb1, ph1); ph1 ^= 1; }                   \
        else    { mwait(mb0, ph0); ph0 ^= 1; }                   \
    } while (0)
#define PIPE_POST() do {                                         \
        __syncthreads();                                         \
        if (qi < NCH) {                                          \
            if (tid == 0)                                        \
                bulk_issue(sl ? wa1 : wa0,                       \
                           (const char*)g_wh + qlist[qi],        \
                           sl ? mb1 : mb0);                      \
            ++qi;                                                \
        }                                                        \
        sl ^= 1;                                                 \
    } while (0)
#define CHUNK(A, AST, KB) do {                                   \
        PIPE_WAIT();                                             \
        mma_chunk4(acc, (A), (AST), (KB), sl ? wbp1 : wbp0,      \
                   mg, ng, lane);                                \
        PIPE_POST();                                             \
    } while (0)

    // ---- layers 0..7 (relu) + final L8 (no relu) ----
    float acc[2][4][4];
    for (int L = 0; L <= 8; ++L) {
        const float* B = (L < 8) ? p.b[L] : p.bf;
        __half* out = (L & 1) ? hbuf1 : hbuf0;
        __half* in  = (L & 1) ? hbuf0 : hbuf1;
#pragma unroll 1
        for (int nh = 0; nh < 2; ++nh) {
            zacc(acc);
            if (L == 0) {
                CHUNK(sX, XSTH, 0);
            } else {
                if (L == 4) CHUNK(sX, XSTH, 0);
#pragma unroll 1
                for (int c = 0; c < 4; ++c)
                    CHUNK(in, HSTH, c * 64);
            }
            epi(acc, out, HSTH, B, nh * 128 + ng * 32, /*relu=*/(L < 8),
                mg, lane);
        }
        __syncthreads();   // next layer reads `out`
    }

    // ---- sigma from h7 (hbuf1; L8 wrote hbuf0) ----
    {
        const int r = tid >> 2, q = tid & 3;
        const __half* hr = hbuf1 + r * HSTH + q * 64;
        const float* ws = p.ws + q * 64;
        float s = 0.0f;
#pragma unroll 8
        for (int i = 0; i < 64; ++i)
            s = fmaf(__half2float(hr[i]), __ldg(ws + i), s);
        s += __shfl_xor_sync(0xffffffffu, s, 1);
        s += __shfl_xor_sync(0xffffffffu, s, 2);
        if (q == 0) sSig[r] = s + __ldg(p.bs);
    }

    // ---- rgb1: relu([final(256) | dir(27 pad 64)] @ w_rgb1 + b_rgb1) ----
    zacc(acc);
#pragma unroll 1
    for (int c = 0; c < 4; ++c)
        CHUNK(hbuf0, HSTH, c * 64);
    CHUNK(sDr, DSTH, 0);
    epi(acc, sHid, HIDH, p.br1, ng * 32, true, mg, lane);
    __syncthreads();

    // ---- rgb2 + sigmoid + output [N,4] = [rgb, sigma] ----
    if (tid < 384) {
        const int r = tid / 3, c = tid % 3;
        float s = __ldg(p.br2 + c);
        const __half* hr = sHid + r * HIDH;
#pragma unroll 8
        for (int k = 0; k < 128; ++k)
            s = fmaf(__half2float(hr[k]), __ldg(p.wr2 + k * 3 + c), s);
        p.out[(p0 + r) * 4 + c] = 1.0f / (1.0f + expf(-s));
    } else {
        const int r = tid - 384;
        p.out[(p0 + r) * 4 + 3] = sSig[r];
    }
#undef PIPE_WAIT
#undef PIPE_POST
#undef CHUNK
}

extern "C" void kernel_launch(void* const* d_in, const int* in_sizes, int n_in,
                              void* d_out, int out_size) {
    Params p;
    p.x = (const float*)d_in[0];
    const float* w[8];
    for (int i = 0; i < 8; ++i) {
        w[i]   = (const float*)d_in[1 + 2 * i];
        p.b[i] = (const float*)d_in[2 + 2 * i];
    }
    const float* wf  = (const float*)d_in[17];
    p.bf  = (const float*)d_in[18];
    p.ws  = (const float*)d_in[19];
    p.bs  = (const float*)d_in[20];
    const float* wr1 = (const float*)d_in[21];
    p.br1 = (const float*)d_in[22];
    p.wr2 = (const float*)d_in[23];
    p.br2 = (const float*)d_in[24];
    p.out = (float*)d_out;

    PackArgs pa;
    pa.s[0]  = { w[0], 256,   0,  63, 1, SEG0 };
    pa.s[1]  = { w[1], 256,   0, 256, 4, SEG1 };
    pa.s[2]  = { w[2], 256,   0, 256, 4, SEG2 };
    pa.s[3]  = { w[3], 256,   0, 256, 4, SEG3 };
    pa.s[4]  = { w[4], 256,   0,  63, 1, SEG4X };
    pa.s[5]  = { w[4], 256,  63, 256, 4, SEG4H };
    pa.s[6]  = { w[5], 256,   0, 256, 4, SEG5 };
    pa.s[7]  = { w[6], 256,   0, 256, 4, SEG6 };
    pa.s[8]  = { w[7], 256,   0, 256, 4, SEG7 };
    pa.s[9]  = { wf,   256,   0, 256, 4, SEGF };
    pa.s[10] = { wr1,  128,   0, 256, 4, SEGR1 };
    pa.s[11] = { wr1,  128, 256,  27, 1, SEGR1D };

    pack_weights<<<(WH_TOTAL + 511) / 512, 512>>>(pa);

    cudaFuncSetAttribute((const void*)nerf_fused,
                         cudaFuncAttributeMaxDynamicSharedMemorySize, SMEM_BYTES);

    const int npts    = in_sizes[0] / 6;
    const int nblocks = npts / MTILE;
    nerf_fused<<<nblocks, BLK, SMEM_BYTES>>>(p);
}

// round 15
// speedup vs baseline: 1.1334x; 1.1334x over previous
#include <cuda_runtime.h>
#include <cuda_fp16.h>

// Fused NeRF MLP forward, fp16 mma.sync.m16n8k16, fp32 accum.
// 128 points/CTA, 512 threads (16 warps = 4 Mgrp x 4 Ngrp).
// Merged-N warp tile 32x64 (two 32-col groups at cb and cb+128): each layer is
// ONE pass over 32KB weight chunks (full N=256), staged by cp.async.bulk
// through a flat double-buffered mbarrier pipeline.

#define MTILE 128
#define BLK   512
#define NCH   39
#define NWIDE 34          // chunks 0..33 are 32KB; 34..38 are 16KB (rgb1)

// strides in halves (row stride bytes % 128 == 16 -> conflict-free ldmatrix)
#define HSTH  264
#define XSTH  72
#define HIDH  136

// ---- packed weight buffer (halves): 32KB wide images / 16KB narrow images --
#define SEG0   0
#define SEG1   16384
#define SEG2   81920
#define SEG3   147456
#define SEG4X  212992
#define SEG4H  229376
#define SEG5   294912
#define SEG6   360448
#define SEG7   425984
#define SEGF   491520
#define SEGR1  557056
#define SEGR1D 589824
#define WH_TOTAL 598016
__device__ __align__(16) __half g_wh[WH_TOTAL];

// ---- smem byte offsets ----
#define OFF_H0   0                   // 128*264*2 = 67584
#define OFF_H1   67584
#define OFF_XD   135168              // 128*72*2 = 18432 (xyz, later dir)
#define OFF_RAW  153600              // 128*6*4 = 3072
#define OFF_W0   156672              // 32768
#define OFF_W1   189440              // 32768
#define OFF_SIG  222208              // 512
#define OFF_MB   222720              // 2 x 8B
#define OFF_LIST 222736              // 39 x 4B
#define OFF_HID  OFF_W0              // rgb hidden aliases dead weight slots
#define SMEM_BYTES 222912

struct Params {
    const float* x;
    const float* b[8];
    const float *bf, *ws, *bs, *br1, *wr2, *br2;
    float* out;
};

// ============ pack kernel: weights -> pre-swizzled chunk images =============
// wide image (N=256): 16384 halves = [pr 0..31][512 halves: 64 swizzled 16B chunks]
// narrow image (N=128): 8192 halves = [pr 0..31][256 halves: 32 chunks]
struct PSeg { const float* src; int ldn; int k0; int k_real; int wide; int dst; };
struct PackArgs { PSeg s[12]; };

__global__ void pack_weights(PackArgs pa) {
    const int idx = blockIdx.x * blockDim.x + threadIdx.x;
    if (idx >= WH_TOTAL) return;
    int si = 0;
#pragma unroll
    for (int i = 1; i < 12; ++i)
        if (idx >= pa.s[i].dst) si = i;
    const PSeg g = pa.s[si];
    const int local = idx - g.dst;
    int img, pr, wh;
    if (g.wide) { img = local >> 14; pr = (local >> 9) & 31; wh = local & 511; }
    else        { img = local >> 13; pr = (local >> 8) & 31; wh = local & 255; }
    const int cs_sw = wh >> 3;
    const int h     = wh & 7;
    const int cs    = cs_sw ^ ((pr & 3) << 1);
    const int n     = cs * 4 + (h >> 1);
    const int krel  = img * 64 + pr * 2 + (h & 1);
    const float v = (krel < g.k_real) ? g.src[(g.k0 + krel) * g.ldn + n] : 0.0f;
    g_wh[idx] = __float2half_rn(v);
}

// ========================= device primitives ================================
__device__ __forceinline__ void mma16(float c[4], const unsigned a[4],
                                      unsigned b0, unsigned b1) {
    asm volatile(
        "mma.sync.aligned.m16n8k16.row.col.f32.f16.f16.f32 "
        "{%0,%1,%2,%3}, {%4,%5,%6,%7}, {%8,%9}, {%0,%1,%2,%3};\n"
        : "+f"(c[0]), "+f"(c[1]), "+f"(c[2]), "+f"(c[3])
        : "r"(a[0]), "r"(a[1]), "r"(a[2]), "r"(a[3]), "r"(b0), "r"(b1));
}
__device__ __forceinline__ void ldsm_x4(unsigned r[4], const __half* p) {
    unsigned addr = (unsigned)__cvta_generic_to_shared(p);
    asm volatile("ldmatrix.sync.aligned.m8n8.x4.shared.b16 {%0,%1,%2,%3}, [%4];\n"
        : "=r"(r[0]), "=r"(r[1]), "=r"(r[2]), "=r"(r[3]) : "r"(addr));
}
__device__ __forceinline__ void mbar_init1(unsigned m) {
    asm volatile("mbarrier.init.shared.b64 [%0], %1;" :: "r"(m), "r"(1u) : "memory");
}
__device__ __forceinline__ void bulk_issue(unsigned dst, const void* src,
                                           unsigned mbar, unsigned bytes) {
    asm volatile("mbarrier.arrive.expect_tx.shared.b64 _, [%0], %1;"
                 :: "r"(mbar), "r"(bytes) : "memory");
    asm volatile(
        "cp.async.bulk.shared::cluster.global.mbarrier::complete_tx::bytes "
        "[%0], [%1], %2, [%3];"
        :: "r"(dst), "l"(src), "r"(bytes), "r"(mbar) : "memory");
}
__device__ __forceinline__ void mwait(unsigned m, int parity) {
    unsigned done;
    do {
        asm volatile("{\n\t.reg .pred p;\n\t"
            "mbarrier.try_wait.parity.acquire.cta.shared::cta.b64 p, [%1], %2, 0x989680;\n\t"
            "selp.b32 %0, 1, 0, p;\n\t}"
            : "=r"(done) : "r"(m), "r"((unsigned)parity) : "memory");
    } while (!done);
}

// Merged chunk: 64 k-rows x 256 N. sW words: [pr 0..31][256].
// Warp covers cols [cb, cb+32) and [cb+128, cb+160), cb = ng*32.
__device__ __forceinline__ void mma_chunk256(float acc[2][8][4],
        const __half* __restrict__ sA, int astH, int kbH,
        const float* __restrict__ sW, int mg, int ng, int lane)
{
    const int g    = lane >> 2;
    const int tig  = lane & 3;
    const int mat  = lane >> 3;
    const int arow = ((mat & 1) << 3) + (lane & 7);
    const int akof = (mat >> 1) << 3;
    const int rb   = mg * 32;
    const int c0   = (((ng << 3) + g) ^ (tig << 1)) << 2;   // word off, half0

#pragma unroll
    for (int s = 0; s < 4; ++s) {
        unsigned a[2][4];
#pragma unroll
        for (int m = 0; m < 2; ++m) {
            const __half* ap = sA + (rb + 16 * m + arow) * astH
                                  + kbH + 16 * s + akof;
            ldsm_x4(a[m], ap);
        }
        const float* r0p = sW + (8 * s + tig) * 256;
        const float* r1p = r0p + 4 * 256;
        const float4 q0 = *(const float4*)(r0p + c0);
        const float4 q1 = *(const float4*)(r1p + c0);
        const float4 q2 = *(const float4*)(r0p + c0 + 128);
        const float4 q3 = *(const float4*)(r1p + c0 + 128);
        const unsigned* b0 = (const unsigned*)&q0;
        const unsigned* b1 = (const unsigned*)&q1;
        const unsigned* b2 = (const unsigned*)&q2;
        const unsigned* b3 = (const unsigned*)&q3;
#pragma unroll
        for (int j = 0; j < 4; ++j) {
            mma16(acc[0][j], a[0], b0[j], b1[j]);
            mma16(acc[1][j], a[1], b0[j], b1[j]);
            mma16(acc[0][4 + j], a[0], b2[j], b3[j]);
            mma16(acc[1][4 + j], a[1], b2[j], b3[j]);
        }
    }
}

// Narrow chunk (rgb1): 64 k-rows x 128 N. sW words: [pr][128]. j = 0..3 only.
__device__ __forceinline__ void mma_chunk128(float acc[2][8][4],
        const __half* __restrict__ sA, int astH, int kbH,
        const float* __restrict__ sW, int mg, int ng, int lane)
{
    const int g    = lane >> 2;
    const int tig  = lane & 3;
    const int mat  = lane >> 3;
    const int arow = ((mat & 1) << 3) + (lane & 7);
    const int akof = (mat >> 1) << 3;
    const int rb   = mg * 32;
    const int c0   = (((ng << 3) + g) ^ (tig << 1)) << 2;

#pragma unroll
    for (int s = 0; s < 4; ++s) {
        unsigned a[2][4];
#pragma unroll
        for (int m = 0; m < 2; ++m) {
            const __half* ap = sA + (rb + 16 * m + arow) * astH
                                  + kbH + 16 * s + akof;
            ldsm_x4(a[m], ap);
        }
        const float* r0p = sW + (8 * s + tig) * 128;
        const float* r1p = r0p + 4 * 128;
        const float4 q0 = *(const float4*)(r0p + c0);
        const float4 q1 = *(const float4*)(r1p + c0);
        const unsigned* b0 = (const unsigned*)&q0;
        const unsigned* b1 = (const unsigned*)&q1;
#pragma unroll
        for (int j = 0; j < 4; ++j) {
            mma16(acc[0][j], a[0], b0[j], b1[j]);
            mma16(acc[1][j], a[1], b0[j], b1[j]);
        }
    }
}

// epilogue for merged tile: cols cb+8*tig(+j) and +128.
__device__ __forceinline__ void epi256(float acc[2][8][4],
        __half* __restrict__ sDst, int dstH,
        const float* __restrict__ gB, bool relu, int mg, int ng, int lane)
{
    const int g   = lane >> 2;
    const int tig = lane & 3;
    const int rb  = mg * 32;
    const int cb0 = ng * 32 + 8 * tig;
#pragma unroll
    for (int half = 0; half < 2; ++half) {
        const int cbase = cb0 + half * 128;
        const float4 bA = *(const float4*)(gB + cbase);
        const float4 bB = *(const float4*)(gB + cbase + 4);
        const float bias[8] = { bA.x, bA.y, bA.z, bA.w, bB.x, bB.y, bB.z, bB.w };
#pragma unroll
        for (int m = 0; m < 2; ++m) {
#pragma unroll
            for (int h = 0; h < 2; ++h) {
                const int row = rb + 16 * m + 8 * h + g;
                __half hv[8];
#pragma unroll
                for (int j = 0; j < 4; ++j) {
                    float v0 = acc[m][4 * half + j][2 * h + 0] + bias[j];
                    float v1 = acc[m][4 * half + j][2 * h + 1] + bias[4 + j];
                    if (relu) { v0 = fmaxf(v0, 0.0f); v1 = fmaxf(v1, 0.0f); }
                    hv[j]     = __float2half_rn(v0);
                    hv[4 + j] = __float2half_rn(v1);
                }
                *(uint4*)(sDst + row * dstH + cbase) = *(const uint4*)hv;
            }
        }
    }
}

// epilogue for narrow (rgb1) tile: j 0..3, cols ng*32 + 8*tig.
__device__ __forceinline__ void epi128(float acc[2][8][4],
        __half* __restrict__ sDst, int dstH,
        const float* __restrict__ gB, int mg, int ng, int lane)
{
    const int g   = lane >> 2;
    const int tig = lane & 3;
    const int rb  = mg * 32;
    const int cbase = ng * 32 + 8 * tig;
    const float4 bA = *(const float4*)(gB + cbase);
    const float4 bB = *(const float4*)(gB + cbase + 4);
    const float bias[8] = { bA.x, bA.y, bA.z, bA.w, bB.x, bB.y, bB.z, bB.w };
#pragma unroll
    for (int m = 0; m < 2; ++m) {
#pragma unroll
        for (int h = 0; h < 2; ++h) {
            const int row = rb + 16 * m + 8 * h + g;
            __half hv[8];
#pragma unroll
            for (int j = 0; j < 4; ++j) {
                float v0 = fmaxf(acc[m][j][2 * h + 0] + bias[j], 0.0f);
                float v1 = fmaxf(acc[m][j][2 * h + 1] + bias[4 + j], 0.0f);
                hv[j]     = __float2half_rn(v0);
                hv[4 + j] = __float2half_rn(v1);
            }
            *(uint4*)(sDst + row * dstH + cbase) = *(const uint4*)hv;
        }
    }
}

__device__ __forceinline__ void zacc(float acc[2][8][4]) {
#pragma unroll
    for (int m = 0; m < 2; ++m)
#pragma unroll
        for (int j = 0; j < 8; ++j)
#pragma unroll
            for (int q = 0; q < 4; ++q) acc[m][j][q] = 0.0f;
}

__global__ void __launch_bounds__(BLK, 1) nerf_fused(Params p) {
    extern __shared__ unsigned char sm[];
    const unsigned sb = (unsigned)__cvta_generic_to_shared(sm);
    __half* hbuf0 = (__half*)(sm + OFF_H0);
    __half* hbuf1 = (__half*)(sm + OFF_H1);
    __half* sXD   = (__half*)(sm + OFF_XD);
    float*  sRaw  = (float*) (sm + OFF_RAW);
    __half* sHid  = (__half*)(sm + OFF_HID);
    float*  sSig  = (float*) (sm + OFF_SIG);
    unsigned* qlist = (unsigned*)(sm + OFF_LIST);

    const unsigned mb0 = sb + OFF_MB, mb1 = sb + OFF_MB + 8;
    const unsigned wa0 = sb + OFF_W0, wa1 = sb + OFF_W1;
    const float* wbp0 = (const float*)(sm + OFF_W0);
    const float* wbp1 = (const float*)(sm + OFF_W1);

    const int tid  = threadIdx.x;
    const int wid  = tid >> 5;
    const int lane = tid & 31;
    const int mg   = wid & 3;
    const int ng   = wid >> 2;
    const int p0   = blockIdx.x * MTILE;

    // ---- init: mbarriers, chunk list, start pipeline; load raw x ----
    if (tid == 0) {
        mbar_init1(mb0);
        mbar_init1(mb1);
        asm volatile("fence.proxy.async.shared::cta;" ::: "memory");
        int i = 0;
        qlist[i++] = SEG0 * 2;
        const int ws[8] = { SEG1, SEG2, SEG3, SEG4H, SEG5, SEG6, SEG7, SEGF };
        for (int L = 1; L <= 8; ++L) {
            if (L == 4) qlist[i++] = SEG4X * 2;
            for (int c = 0; c < 4; ++c)
                qlist[i++] = (ws[L - 1] + c * 16384) * 2;
        }
        for (int c = 0; c < 4; ++c) qlist[i++] = (SEGR1 + c * 8192) * 2;
        qlist[i++] = SEGR1D * 2;
        bulk_issue(wa0, (const char*)g_wh + qlist[0], mb0, 32768u);
        bulk_issue(wa1, (const char*)g_wh + qlist[1], mb1, 32768u);
    }
    for (int idx = tid; idx < MTILE * 6; idx += BLK)
        sRaw[idx] = p.x[p0 * 6 + idx];
    __syncthreads();

    // ---- xyz posenc into XD tile ----
    for (int idx = tid; idx < MTILE * 64; idx += BLK) {
        const int r = idx >> 6, c = idx & 63;
        float v = 0.0f;
        if (c < 3) v = sRaw[r * 6 + c];
        else if (c < 63) {
            const int q = c - 3, f = q / 6, rem = q % 6;
            const float ang = sRaw[r * 6 + (rem % 3)] * (float)(1 << f);
            v = (rem < 3) ? sinf(ang) : cosf(ang);
        }
        sXD[r * XSTH + c] = __float2half_rn(v);
    }
    __syncthreads();

    int sl = 0, ph0 = 0, ph1 = 0, qi = 2;

#define PIPE_WAIT() do {                                         \
        if (sl) { mwait(mb1, ph1); ph1 ^= 1; }                   \
        else    { mwait(mb0, ph0); ph0 ^= 1; }                   \
    } while (0)
#define PIPE_POST() do {                                         \
        __syncthreads();                                         \
        if (qi < NCH) {                                          \
            if (tid == 0)                                        \
                bulk_issue(sl ? wa1 : wa0,                       \
                           (const char*)g_wh + qlist[qi],        \
                           sl ? mb1 : mb0,                       \
                           qi < NWIDE ? 32768u : 16384u);        \
            ++qi;                                                \
        }                                                        \
        sl ^= 1;                                                 \
    } while (0)
#define CHUNK256(A, AST, KB) do {                                \
        PIPE_WAIT();                                             \
        mma_chunk256(acc, (A), (AST), (KB), sl ? wbp1 : wbp0,    \
                     mg, ng, lane);                              \
        PIPE_POST();                                             \
    } while (0)
#define CHUNK128(A, AST, KB) do {                                \
        PIPE_WAIT();                                             \
        mma_chunk128(acc, (A), (AST), (KB), sl ? wbp1 : wbp0,    \
                     mg, ng, lane);                              \
        PIPE_POST();                                             \
    } while (0)

    // ---- layers 0..7 (relu) + final L8 (no relu); one merged pass each ----
    float acc[2][8][4];
    for (int L = 0; L <= 8; ++L) {
        const float* B = (L < 8) ? p.b[L] : p.bf;
        __half* out = (L & 1) ? hbuf1 : hbuf0;
        __half* in  = (L & 1) ? hbuf0 : hbuf1;
        zacc(acc);
        if (L == 0) {
            CHUNK256(sXD, XSTH, 0);
        } else {
            if (L == 4) CHUNK256(sXD, XSTH, 0);
#pragma unroll 1
            for (int c = 0; c < 4; ++c)
                CHUNK256(in, HSTH, c * 64);
        }
        epi256(acc, out, HSTH, B, /*relu=*/(L < 8), mg, ng, lane);
        __syncthreads();   // next layer reads `out`
    }

    // ---- sigma from h7 (hbuf1; L8 wrote hbuf0) ----
    {
        const int r = tid >> 2, q = tid & 3;
        const __half* hr = hbuf1 + r * HSTH + q * 64;
        const float* ws = p.ws + q * 64;
        float s = 0.0f;
#pragma unroll 8
        for (int i = 0; i < 64; ++i)
            s = fmaf(__half2float(hr[i]), __ldg(ws + i), s);
        s += __shfl_xor_sync(0xffffffffu, s, 1);
        s += __shfl_xor_sync(0xffffffffu, s, 2);
        if (q == 0) sSig[r] = s + __ldg(p.bs);
    }

    // ---- dir posenc into XD tile (xyz no longer needed) ----
    for (int idx = tid; idx < MTILE * 64; idx += BLK) {
        const int r = idx >> 6, c = idx & 63;
        float v = 0.0f;
        if (c < 3) v = sRaw[r * 6 + 3 + c];
        else if (c < 27) {
            const int q = c - 3, f = q / 6, rem = q % 6;
            const float ang = sRaw[r * 6 + 3 + (rem % 3)] * (float)(1 << f);
            v = (rem < 3) ? sinf(ang) : cosf(ang);
        }
        sXD[r * XSTH + c] = __float2half_rn(v);
    }
    __syncthreads();

    // ---- rgb1: relu([final(256) | dir(27 pad 64)] @ w_rgb1 + b_rgb1) ----
    zacc(acc);
#pragma unroll 1
    for (int c = 0; c < 4; ++c)
        CHUNK128(hbuf0, HSTH, c * 64);
    CHUNK128(sXD, XSTH, 0);
    epi128(acc, sHid, HIDH, p.br1, mg, ng, lane);   // sHid aliases dead W slots
    __syncthreads();

    // ---- rgb2 + sigmoid + output [N,4] = [rgb, sigma] ----
    if (tid < 384) {
        const int r = tid / 3, c = tid % 3;
        float s = __ldg(p.br2 + c);
        const __half* hr = sHid + r * HIDH;
#pragma unroll 8
        for (int k = 0; k < 128; ++k)
            s = fmaf(__half2float(hr[k]), __ldg(p.wr2 + k * 3 + c), s);
        p.out[(p0 + r) * 4 + c] = 1.0f / (1.0f + expf(-s));
    } else {
        const int r = tid - 384;
        p.out[(p0 + r) * 4 + 3] = sSig[r];
    }
#undef PIPE_WAIT
#undef PIPE_POST
#undef CHUNK256
#undef CHUNK128
}

extern "C" void kernel_launch(void* const* d_in, const int* in_sizes, int n_in,
                              void* d_out, int out_size) {
    Params p;
    p.x = (const float*)d_in[0];
    const float* w[8];
    for (int i = 0; i < 8; ++i) {
        w[i]   = (const float*)d_in[1 + 2 * i];
        p.b[i] = (const float*)d_in[2 + 2 * i];
    }
    const float* wf  = (const float*)d_in[17];
    p.bf  = (const float*)d_in[18];
    p.ws  = (const float*)d_in[19];
    p.bs  = (const float*)d_in[20];
    const float* wr1 = (const float*)d_in[21];
    p.br1 = (const float*)d_in[22];
    p.wr2 = (const float*)d_in[23];
    p.br2 = (const float*)d_in[24];
    p.out = (float*)d_out;

    PackArgs pa;
    pa.s[0]  = { w[0], 256,   0,  63, 1, SEG0 };
    pa.s[1]  = { w[1], 256,   0, 256, 1, SEG1 };
    pa.s[2]  = { w[2], 256,   0, 256, 1, SEG2 };
    pa.s[3]  = { w[3], 256,   0, 256, 1, SEG3 };
    pa.s[4]  = { w[4], 256,   0,  63, 1, SEG4X };
    pa.s[5]  = { w[4], 256,  63, 256, 1, SEG4H };
    pa.s[6]  = { w[5], 256,   0, 256, 1, SEG5 };
    pa.s[7]  = { w[6], 256,   0, 256, 1, SEG6 };
    pa.s[8]  = { w[7], 256,   0, 256, 1, SEG7 };
    pa.s[9]  = { wf,   256,   0, 256, 1, SEGF };
    pa.s[10] = { wr1,  128,   0, 256, 0, SEGR1 };
    pa.s[11] = { wr1,  128, 256,  27, 0, SEGR1D };

    pack_weights<<<(WH_TOTAL + 511) / 512, 512>>>(pa);

    cudaFuncSetAttribute((const void*)nerf_fused,
                         cudaFuncAttributeMaxDynamicSharedMemorySize, SMEM_BYTES);

    const int npts    = in_sizes[0] / 6;
    const int nblocks = npts / MTILE;
    nerf_fused<<<nblocks, BLK, SMEM_BYTES>>>(p);
}